// round 15
// baseline (speedup 1.0000x reference)
#include <cuda_runtime.h>
#include <math.h>

#define Bv 32
#define Cv 1024
#define BC_TOTAL (Bv * Cv)      // 32768
#define HW 784                  // 28*28
#define NMASK 154               // 153 masks + 1 global-max term
#define CHB 64                  // channels per block
#define K1_BLOCKS (BC_TOTAL / CHB)   // 512
#define PITCH 28                // words/channel/tile (4*odd -> conflict-free .128)
#define BUFW (CHB * PITCH)      // 1792 words = 7168 B per buffer
#define NBUF 6
#define DEPTH 4
#define NTILE 28                // one row per tile
#define K1_SMEM (NBUF * BUFW * 4)    // 43008 B
// occupancy: smem->5/SM, regs(64 via launch_bounds)->4/SM, threads->8/SM
// => 4 blocks/SM * 148 = 592 >= 512: ENTIRE GRID RESIDENT (spin-safe)

// ---- static device scratch (no allocations allowed) ----
__device__ float g_sqpart[NMASK * K1_BLOCKS]; // per-block partial squared sums
__device__ int   g_ctr = 0;                   // grid-barrier arrival counter
__device__ int   g_ctr2 = 0;                  // completion counter (resets both)

// ------------------------------------------------------------------
// Compile-time per-(quadrant, tile) GROUP lists. Tile t = row t;
// pixel pp = col stored linearly at word pp. Entry = (4G) | c0<<12 |
// c1<<17 | c2<<22 | c3<<27; code: 0 skip, 1..19 ring rad, 30 corner
// (gm-only, first containing quadrant), 31 center (q0 only).
// Quadrants (ref order): q0 (dx>=0,dy>=0) q1 (dx<=0,dy>=0)
//                        q2 (dx>=0,dy<=0) q3 (dx<=0,dy<=0)
// ------------------------------------------------------------------
struct GLists { unsigned int e[4][NTILE][8]; int cnt[4][NTILE]; };
static constexpr GLists make_glists() {
    GLists L = {};
    for (int q = 0; q < 4; q++) for (int t = 0; t < NTILE; t++) L.cnt[q][t] = 0;
    for (int t = 0; t < NTILE; t++)
        for (int G = 0; G < 7; G++) {
            int codes[4][4] = {};
            bool any[4] = { false, false, false, false };
            for (int k = 0; k < 4; k++) {
                int col = 4 * G + k;
                int dx = col - 14, dy = t - 14;
                int r2 = dx * dx + dy * dy;
                if (r2 == 0) { codes[0][k] = 31; any[0] = true; continue; }
                bool inq[4] = { dx >= 0 && dy >= 0, dx <= 0 && dy >= 0,
                                dx >= 0 && dy <= 0, dx <= 0 && dy <= 0 };
                if (r2 > 361) {
                    for (int q = 0; q < 4; q++)
                        if (inq[q]) { codes[q][k] = 30; any[q] = true; break; }
                } else {
                    int rad = 1; while (rad * rad < r2) rad++;
                    for (int q = 0; q < 4; q++)
                        if (inq[q]) { codes[q][k] = rad; any[q] = true; }
                }
            }
            for (int q = 0; q < 4; q++)
                if (any[q]) {
                    unsigned int e = (unsigned)(4 * G)
                        | ((unsigned)codes[q][0] << 12) | ((unsigned)codes[q][1] << 17)
                        | ((unsigned)codes[q][2] << 22) | ((unsigned)codes[q][3] << 27);
                    L.e[q][t][L.cnt[q][t]++] = e;
                }
        }
    return L;
}
static constexpr GLists GL = make_glists();

// ------------------------------------------------------------------
// cp.async helpers
// ------------------------------------------------------------------
__device__ __forceinline__ void cp_async16(unsigned int dst, const float4* src) {
    asm volatile("cp.async.cg.shared.global [%0], [%1], 16;" :: "r"(dst), "l"(src));
}
#define CP_COMMIT() asm volatile("cp.async.commit_group;" ::: "memory")
template<int N>
__device__ __forceinline__ void cp_wait() {
    asm volatile("cp.async.wait_group %0;" :: "n"(N) : "memory");
}

// ------------------------------------------------------------------
// Consume: fully unrolled; one LDS.128 per group (uniform broadcast),
// per-pixel codes fold to immediates; ring accumulators r[19] in regs.
// ------------------------------------------------------------------
template<int C>
__device__ __forceinline__ void procc(float v, float* r, float& gm0, float& cen) {
    if constexpr (C == 31) { cen = v; }
    else if constexpr (C == 30) { gm0 = fmaxf(gm0, v); }
    else if constexpr (C >= 1) { r[C - 1] = fmaxf(r[C - 1], v); }
}

template<int Q, int T, int K, int N>
struct Steps {
    __device__ __forceinline__ static void run(const float* sxc, float* r,
                                               float& gm0, float& cen) {
        constexpr unsigned e = GL.e[Q][T][K];
        float4 v = *(const float4*)(sxc + (e & 0xFFF));
        procc<((e >> 12) & 31)>(v.x, r, gm0, cen);
        procc<((e >> 17) & 31)>(v.y, r, gm0, cen);
        procc<((e >> 22) & 31)>(v.z, r, gm0, cen);
        procc<((e >> 27) & 31)>(v.w, r, gm0, cen);
        Steps<Q, T, K + 1, N>::run(sxc, r, gm0, cen);
    }
};
template<int Q, int T, int N>
struct Steps<Q, T, N, N> {
    __device__ __forceinline__ static void run(const float*, float*, float&, float&) {}
};

// Stage tile T (row T) into buffer T%NBUF: 64 ch x 7 float4 = 448
// coalesced 16 B cp.async copies (112 B/channel).
template<int T>
__device__ __forceinline__ void stage_tile(const float4* __restrict__ gsrc,
                                           unsigned int sxa, int tid) {
    const unsigned int boff = (unsigned)((T % NBUF) * BUFW) * 4;
#pragma unroll
    for (int it = 0; it < 2; it++) {
        int m = tid + it * 256;
        if (it == 0 || tid < 192) {           // 448 copies total
            int ch = m / 7, f = m % 7;
            cp_async16(sxa + boff + (unsigned)(ch * PITCH + 4 * f) * 4,
                       gsrc + (size_t)ch * (HW / 4) + T * 7 + f);
        }
    }
    CP_COMMIT();
}

template<int T>
__device__ __forceinline__ void consume_dispatch(int q, const float* sxc, float* r,
                                                 float& gm0, float& cen) {
    if (q == 0)      Steps<0, T, 0, GL.cnt[0][T]>::run(sxc, r, gm0, cen);
    else if (q == 1) Steps<1, T, 0, GL.cnt[1][T]>::run(sxc, r, gm0, cen);
    else if (q == 2) Steps<2, T, 0, GL.cnt[2][T]>::run(sxc, r, gm0, cen);
    else             Steps<3, T, 0, GL.cnt[3][T]>::run(sxc, r, gm0, cen);
}

// Depth-4 pipeline, NBUF=6, ONE sync per tile. WAR safety: staging
// T+4 targets buffer (T-2)%6, consumed at tile T-2; every warp has
// passed the pre-consume sync of tile T-1, which in its program
// order follows its consume of T-2.
template<int T>
__device__ __forceinline__ void tiles(const float4* __restrict__ gsrc,
                                      unsigned int sxa, float* sx, int tid, int q,
                                      int ch, float* r, float& gm0, float& cen) {
    if constexpr (T + DEPTH < NTILE) {
        stage_tile<T + DEPTH>(gsrc, sxa, tid);
        cp_wait<DEPTH>();
    } else {
        cp_wait<NTILE - 1 - T>();
    }
    __syncthreads();
    consume_dispatch<T>(q, sx + (T % NBUF) * BUFW + ch * PITCH, r, gm0, cen);
    if constexpr (T + 1 < NTILE) tiles<T + 1>(gsrc, sxa, sx, tid, q, ch, r, gm0, cen);
}

// ------------------------------------------------------------------
// FUSED kernel: phase 1 streams x (ring maxes in regs, squared-norm
// partials -> g_sqpart); grid spin-barrier; phase 2 rebuilds rn from
// partials and finishes normalize-accumulate FROM REGISTERS (no
// intermediate state tensor at all).
// ------------------------------------------------------------------
__global__ __launch_bounds__(256, 4) void k_fused(const float* __restrict__ x,
                                                  float* __restrict__ out) {
    extern __shared__ __align__(16) float sx[];        // NBUF x 7168 B
    int tid = threadIdx.x;
    int q = tid >> 6;                 // 64-thread (2-warp) quadrant group
    int ch = tid & 63;
    int lane = tid & 31;
    int half = (tid >> 5) & 1;
    int blk = blockIdx.x;
    int bc0 = blk * CHB;

    unsigned int sxa = (unsigned int)__cvta_generic_to_shared(sx);
    const float4* gsrc = (const float4*)(x + (size_t)bc0 * HW);
    float r[19];
#pragma unroll
    for (int i = 0; i < 19; i++) r[i] = -INFINITY;
    float gm0 = -INFINITY, cen = 0.0f;

    stage_tile<0>(gsrc, sxa, tid);
    stage_tile<1>(gsrc, sxa, tid);
    stage_tile<2>(gsrc, sxa, tid);
    stage_tile<3>(gsrc, sxa, tid);
    tiles<0>(gsrc, sxa, sx, tid, q, ch, r, gm0, cen);

    // ---- phase-1 epilogue: squared-norm partials only ----
    float* scen = sx;                 // [64]
    float* sgm = sx + 64;             // [4][64]
    float* spart = sx + 320;          // [NMASK][2]
    float* srn = sx + 640;            // [NMASK]   (phase 2)
    float* part = sx + 800;           // [4][64]   (phase 2)

    __syncthreads();                  // all consumes done; overlay safe
    if (q == 0) scen[ch] = cen;
    __syncthreads();
    float centerv = scen[ch];

    float gmq = fmaxf(gm0, centerv);
#pragma unroll
    for (int i = 0; i < 19; i++) gmq = fmaxf(gmq, r[i]);
    sgm[q * 64 + ch] = gmq;
    __syncthreads();
    float gmf = fmaxf(fmaxf(sgm[ch], sgm[64 + ch]),
                      fmaxf(sgm[128 + ch], sgm[192 + ch]));

#define WRED(m, val) { float _s = (val) * (val); \
    _s += __shfl_xor_sync(0xffffffffu, _s, 16); \
    _s += __shfl_xor_sync(0xffffffffu, _s, 8); \
    _s += __shfl_xor_sync(0xffffffffu, _s, 4); \
    _s += __shfl_xor_sync(0xffffffffu, _s, 2); \
    _s += __shfl_xor_sync(0xffffffffu, _s, 1); \
    if (lane == 0) spart[(m) * 2 + half] = _s; }

    if (q == 0) {
        WRED(0, fmaxf(centerv, 0.0f));
        WRED(153, gmf);
    }
    {
        float c = centerv;
#pragma unroll
        for (int rad = 1; rad <= 19; rad++) {
            float rv = r[rad - 1];
            c = fmaxf(c, rv);
            int mb = 1 + (rad - 1) * 8 + q * 2;
            WRED(mb, fmaxf(rv, 0.0f));
            WRED(mb + 1, fmaxf(c, 0.0f));
        }
    }
#undef WRED

    __syncthreads();
    if (tid < NMASK)
        g_sqpart[tid * K1_BLOCKS + blk] = spart[tid * 2] + spart[tid * 2 + 1];

    // ---- grid barrier (entire grid resident: 4 blocks/SM x 148) ----
    __syncthreads();
    if (tid == 0) {
        __threadfence();              // release g_sqpart writes
        atomicAdd(&g_ctr, 1);
        while (*((volatile int*)&g_ctr) < K1_BLOCKS) { __nanosleep(64); }
        __threadfence();              // acquire peers' g_sqpart writes
    }
    __syncthreads();

    // ---- phase 2a: rn for this batch (warp per mask, lanes 0..15) ----
    int b = blk >> 3;                 // 8 blocks per batch (512/32... )
    b = blk / (K1_BLOCKS / Bv);       // = blk / 16
    int w8 = tid >> 5;
    for (int m = w8; m < NMASK; m += 8) {
        float s = (lane < 16)
            ? __ldcg(&g_sqpart[m * K1_BLOCKS + b * (K1_BLOCKS / Bv) + lane])
            : 0.0f;
#pragma unroll
        for (int o = 16; o; o >>= 1) s += __shfl_xor_sync(0xffffffffu, s, o);
        if (lane == 0) srn[m] = 1.0f / (sqrtf(s) + 1e-6f);
    }
    __syncthreads();

    // ---- phase 2b: normalize-accumulate from registers ----
    float c = centerv;
    float acc = 0.0f;
#pragma unroll
    for (int rad = 1; rad <= 19; rad++) {
        float rv = r[rad - 1];
        c = fmaxf(c, rv);
        int mb = 1 + (rad - 1) * 8 + q * 2;
        acc += fmaxf(rv, 0.0f) * srn[mb] + fmaxf(c, 0.0f) * srn[mb + 1];
    }
    if (q == 0)
        acc += fmaxf(centerv, 0.0f) * srn[0] + gmf * srn[153];
    part[q * 64 + ch] = acc;
    __syncthreads();
    if (tid < 64)
        out[bc0 + tid] = part[tid] + part[64 + tid] + part[128 + tid] + part[192 + tid];

    // ---- reset counters for next launch (all spinners have exited) ----
    if (tid == 0) {
        int o2 = atomicAdd(&g_ctr2, 1);
        if (o2 == K1_BLOCKS - 1) { g_ctr = 0; g_ctr2 = 0; }
    }
}

extern "C" void kernel_launch(void* const* d_in, const int* in_sizes, int n_in,
                              void* d_out, int out_size) {
    const float* x = (const float*)d_in[0];
    float* out = (float*)d_out;
    cudaFuncSetAttribute(k_fused, cudaFuncAttributeMaxDynamicSharedMemorySize, K1_SMEM);
    k_fused<<<K1_BLOCKS, 256, K1_SMEM>>>(x, out);
}